// round 12
// baseline (speedup 1.0000x reference)
#include <cuda_runtime.h>
#include <cuda_fp16.h>
#include <cstdint>
#include <cstddef>

// ============================================================================
// EGNN layer: h' = h + MLP_u([h, scatter_add(MLP_m([h_s, h_r, dist]))])
//
// Layer-1 of the edge MLP is linear in gathered features -> node-level GEMMs
// P = h@W1a^T, Q = h@W1b^T. Edges are counting-sorted by receiver so the
// fused edge kernel (gather -> silu -> fp16 MMA -> silu) can do a SEGMENTED
// reduction: one float4 atomic per receiver-run instead of per edge row.
// ============================================================================

#define DD 128
#define NMAX 50176   // >= N = 50000
#define EMAX 800000  // == E

__device__ __align__(16) float g_P[(size_t)NMAX * DD];
__device__ __align__(16) float g_Q[(size_t)NMAX * DD];
__device__ __align__(16) float g_agg[(size_t)NMAX * DD];
__device__ __align__(16) float g_u1[(size_t)NMAX * DD];
// counting-sort scratch
__device__ int g_cnt[NMAX];
__device__ int g_cur[NMAX];
__device__ int g_baseb[NMAX];
__device__ int g_es[EMAX];   // sorted sender
__device__ int g_er[EMAX];   // sorted receiver (ascending)

__device__ __forceinline__ float* resolve_buf(int code, const float* ext) {
    switch (code) {
        case 1: return g_P;
        case 2: return g_Q;
        case 3: return g_agg;
        case 4: return g_u1;
        default: return (float*)ext;
    }
}

__device__ __forceinline__ float silu_f(float x) {
    float t;
    asm("tanh.approx.f32 %0, %1;" : "=f"(t) : "f"(0.5f * x));
    return 0.5f * x * (1.f + t);
}
__device__ __forceinline__ float2 silu2_f(float x0, float x1) {
    __half2 ph = __floats2half2_rn(0.5f * x0, 0.5f * x1);
    uint32_t pu = *(uint32_t*)&ph, tu;
    asm("tanh.approx.f16x2 %0, %1;" : "=r"(tu) : "r"(pu));
    float2 tf = __half22float2(*(__half2*)&tu);
    return make_float2(0.5f * x0 * (1.f + tf.x), 0.5f * x1 * (1.f + tf.y));
}
__device__ __forceinline__ float tf32r(float x) {
    uint32_t u;
    asm("cvt.rna.tf32.f32 %0, %1;" : "=r"(u) : "f"(x));
    return __uint_as_float(u);
}
__device__ __forceinline__ void mma8(float* c, const uint32_t* a, const uint32_t* b) {
    asm volatile(
        "mma.sync.aligned.m16n8k8.row.col.f32.tf32.tf32.f32 "
        "{%0,%1,%2,%3},{%4,%5,%6,%7},{%8,%9},{%0,%1,%2,%3};\n"
        : "+f"(c[0]), "+f"(c[1]), "+f"(c[2]), "+f"(c[3])
        : "r"(a[0]), "r"(a[1]), "r"(a[2]), "r"(a[3]), "r"(b[0]), "r"(b[1]));
}
__device__ __forceinline__ void mma16(float* c, const uint32_t* a, const uint32_t* b) {
    asm volatile(
        "mma.sync.aligned.m16n8k16.row.col.f32.f16.f16.f32 "
        "{%0,%1,%2,%3},{%4,%5,%6,%7},{%8,%9},{%0,%1,%2,%3};\n"
        : "+f"(c[0]), "+f"(c[1]), "+f"(c[2]), "+f"(c[3])
        : "r"(a[0]), "r"(a[1]), "r"(a[2]), "r"(a[3]), "r"(b[0]), "r"(b[1]));
}

// ============================================================================
// Counting sort by receiver
// ============================================================================
__global__ void zero_scratch(int N, int n4) {
    int i = blockIdx.x * 256 + threadIdx.x;
    if (i < n4) ((float4*)g_agg)[i] = make_float4(0.f, 0.f, 0.f, 0.f);
    if (i < N) { g_cnt[i] = 0; g_cur[i] = 0; }
}

__global__ void hist_kernel(const int* __restrict__ ei, int E) {
    int e = blockIdx.x * 256 + threadIdx.x;
    if (e < E) atomicAdd(&g_cnt[ei[(size_t)E + e]], 1);
}

// single-block exclusive scan of g_cnt[0..N) -> g_baseb
__global__ __launch_bounds__(1024) void scan_kernel(int N) {
    __shared__ int warp_sums[32];
    __shared__ int run_s;
    int tid = threadIdx.x;
    if (tid == 0) run_s = 0;
    __syncthreads();
    int nChunks = (N + 1023) / 1024;
    for (int c = 0; c < nChunks; ++c) {
        int idx = c * 1024 + tid;
        int v = (idx < N) ? g_cnt[idx] : 0;
        int x = v;
#pragma unroll
        for (int o = 1; o < 32; o <<= 1) {
            int y = __shfl_up_sync(0xffffffffu, x, o);
            if ((tid & 31) >= o) x += y;
        }
        if ((tid & 31) == 31) warp_sums[tid >> 5] = x;
        __syncthreads();
        if (tid < 32) {
            int s = warp_sums[tid];
#pragma unroll
            for (int o = 1; o < 32; o <<= 1) {
                int y = __shfl_up_sync(0xffffffffu, s, o);
                if (tid >= o) s += y;
            }
            warp_sums[tid] = s;
        }
        __syncthreads();
        int incl = x + ((tid >= 32) ? warp_sums[(tid >> 5) - 1] : 0);
        int excl = incl - v + run_s;
        if (idx < N) g_baseb[idx] = excl;
        __syncthreads();
        if (tid == 1023) run_s = excl + v;
        __syncthreads();
    }
}

__global__ void scatter_kernel(const int* __restrict__ ei, int E) {
    int e = blockIdx.x * 256 + threadIdx.x;
    if (e >= E) return;
    int s = ei[e];
    int r = ei[(size_t)E + e];
    int pos = g_baseb[r] + atomicAdd(&g_cur[r], 1);
    g_es[pos] = s;
    g_er[pos] = r;
}

// ============================================================================
// Node-level GEMM (tf32): out[M,128] = epi( sum_p A_p[M,128] @ B_p^T )
// mode 0: raw; 1: silu(acc+bias); 2: acc+bias+resid.
// ============================================================================
__global__ __launch_bounds__(256) void gemm_node(
    const float* __restrict__ A0e, int a0c,
    const float* __restrict__ B0, int ldb0,
    int a1c, const float* __restrict__ B1, int ldb1,
    const float* __restrict__ bias, const float* __restrict__ resid,
    float* __restrict__ oute, int outc, int M, int mode)
{
    __shared__ float As[128][36];
    __shared__ float Bs[128][36];
    int tid = threadIdx.x;
    int warp = tid >> 5, ln = tid & 31;
    int m0 = blockIdx.x * 128;

    const float* A0 = resolve_buf(a0c, A0e);
    const float* A1 = (a1c == 0) ? nullptr : resolve_buf(a1c, nullptr);
    float* out = resolve_buf(outc, oute);

    float acc[16][4];
#pragma unroll
    for (int i = 0; i < 16; ++i) {
        acc[i][0] = 0.f; acc[i][1] = 0.f; acc[i][2] = 0.f; acc[i][3] = 0.f;
    }

    for (int p = 0; p < 2; ++p) {
        const float* A = p ? A1 : A0;
        const float* B = p ? B1 : B0;
        int ldb = p ? ldb1 : ldb0;
        if (!A) continue;
        for (int k0 = 0; k0 < 128; k0 += 32) {
#pragma unroll
            for (int i = 0; i < 4; ++i) {
                int r = (tid >> 3) + i * 32;
                int c = (tid & 7) * 4;
                float4 v = make_float4(0.f, 0.f, 0.f, 0.f);
                int gr = m0 + r;
                if (gr < M) v = *(const float4*)(A + (size_t)gr * 128 + k0 + c);
                v.x = tf32r(v.x); v.y = tf32r(v.y); v.z = tf32r(v.z); v.w = tf32r(v.w);
                *(float4*)&As[r][c] = v;
            }
#pragma unroll
            for (int i = 0; i < 4; ++i) {
                int n = (tid >> 3) + i * 32;
                int c = (tid & 7) * 4;
                const float* bp = B + (size_t)n * ldb + k0 + c;
                Bs[n][c + 0] = tf32r(bp[0]);
                Bs[n][c + 1] = tf32r(bp[1]);
                Bs[n][c + 2] = tf32r(bp[2]);
                Bs[n][c + 3] = tf32r(bp[3]);
            }
            __syncthreads();

            int srow = warp * 16 + (ln >> 2);
            int scol = ln & 3;
#pragma unroll
            for (int kk = 0; kk < 4; ++kk) {
                uint32_t a[4];
                a[0] = __float_as_uint(As[srow][kk * 8 + scol]);
                a[1] = __float_as_uint(As[srow + 8][kk * 8 + scol]);
                a[2] = __float_as_uint(As[srow][kk * 8 + scol + 4]);
                a[3] = __float_as_uint(As[srow + 8][kk * 8 + scol + 4]);
#pragma unroll
                for (int nt = 0; nt < 16; ++nt) {
                    uint32_t b[2];
                    b[0] = __float_as_uint(Bs[nt * 8 + (ln >> 2)][kk * 8 + scol]);
                    b[1] = __float_as_uint(Bs[nt * 8 + (ln >> 2)][kk * 8 + scol + 4]);
                    mma8(acc[nt], a, b);
                }
            }
            __syncthreads();
        }
    }

    int r0 = m0 + warp * 16 + (ln >> 2);
    int c0 = (ln & 3) * 2;
#pragma unroll
    for (int nt = 0; nt < 16; ++nt) {
        int col = nt * 8 + c0;
#pragma unroll
        for (int h8 = 0; h8 < 2; ++h8) {
            int row = r0 + h8 * 8;
            if (row >= M) continue;
#pragma unroll
            for (int q = 0; q < 2; ++q) {
                float v = acc[nt][h8 * 2 + q];
                int cc = col + q;
                if (mode == 1)      v = silu_f(v + bias[cc]);
                else if (mode == 2) v = v + bias[cc] + resid[(size_t)row * 128 + cc];
                out[(size_t)row * 128 + cc] = v;
            }
        }
    }
}

// ============================================================================
// Edge kernel v5: round-6 v2 mainloop + receiver-sorted input + segmented
// float4-atomic reduction epilogue.
// 64 edges/block, 256 threads, warp w covers cols [16w,16w+16), fp16 MMA.
// ============================================================================
#define AS_LD 136   // half stride
#define MS_LD 132   // float stride

__global__ __launch_bounds__(256) void edge_kernel(
    const float* __restrict__ coords,
    const float* __restrict__ W1, const float* __restrict__ b1,
    const float* __restrict__ W2, const float* __restrict__ b2,
    int E)
{
    __shared__ __align__(16) char buf[64 * MS_LD * 4];  // 33792 B, aliased
    __shared__ int   s_sh[64];
    __shared__ int   r_sh[64];
    __shared__ float dist_sh[64];
    __shared__ float b1s[128];
    __shared__ float w1cs[128];
    __shared__ float b2s[128];

    half  (*As)[AS_LD] = (half(*)[AS_LD])buf;
    float (*Ms)[MS_LD] = (float(*)[MS_LD])buf;

    int tid = threadIdx.x;
    int warp = tid >> 5, ln = tid & 31;
    int e0 = blockIdx.x * 64;

    // meta: sorted edges
    if (tid < 64) {
        int e = e0 + tid;
        int s = 0, r = -1;
        float d = 0.f;
        if (e < E) {
            s = g_es[e];
            r = g_er[e];
            float dx = coords[s * 3 + 0] - coords[r * 3 + 0];
            float dy = coords[s * 3 + 1] - coords[r * 3 + 1];
            float dz = coords[s * 3 + 2] - coords[r * 3 + 2];
            d = sqrtf(dx * dx + dy * dy + dz * dz);
        }
        s_sh[tid] = s; r_sh[tid] = r; dist_sh[tid] = d;
    }
    if (tid < 128) {
        b1s[tid]  = b1[tid];
        w1cs[tid] = W1[(size_t)tid * 257 + 256];
        b2s[tid]  = b2[tid];
    }

    // W2 -> per-warp fp16 register fragments. warp w owns cols [16w,16w+16).
    uint32_t breg[2][8][2];
#pragma unroll
    for (int nt = 0; nt < 2; ++nt) {
        int n = warp * 16 + nt * 8 + (ln >> 2);
#pragma unroll
        for (int kc = 0; kc < 8; ++kc) {
            int k0 = kc * 16 + (ln & 3) * 2;
            float2 lo = *(const float2*)(W2 + (size_t)n * 128 + k0);
            float2 hi = *(const float2*)(W2 + (size_t)n * 128 + k0 + 8);
            __half2 hlo = __floats2half2_rn(lo.x, lo.y);
            __half2 hhi = __floats2half2_rn(hi.x, hi.y);
            breg[nt][kc][0] = *(uint32_t*)&hlo;
            breg[nt][kc][1] = *(uint32_t*)&hhi;
        }
    }
    __syncthreads();

    // gather + layer-1 + silu -> As (fp16). Q[r] repeats within tile -> L1 hits.
#pragma unroll
    for (int it = 0; it < 8; ++it) {
        int idx = tid + it * 256;
        int i = idx >> 5;
        int j = (idx & 31) * 4;
        int s = s_sh[i], r = r_sh[i];
        float2 v01 = make_float2(0.f, 0.f), v23 = make_float2(0.f, 0.f);
        if (r >= 0) {
            float d = dist_sh[i];
            float4 pv = *(const float4*)(g_P + (size_t)s * 128 + j);
            float4 qv = *(const float4*)(g_Q + (size_t)r * 128 + j);
            float x0 = pv.x + qv.x + d * w1cs[j + 0] + b1s[j + 0];
            float x1 = pv.y + qv.y + d * w1cs[j + 1] + b1s[j + 1];
            float x2 = pv.z + qv.z + d * w1cs[j + 2] + b1s[j + 2];
            float x3 = pv.w + qv.w + d * w1cs[j + 3] + b1s[j + 3];
            v01 = silu2_f(x0, x1);
            v23 = silu2_f(x2, x3);
        }
        __half2 h0 = __floats2half2_rn(v01.x, v01.y);
        __half2 h1 = __floats2half2_rn(v23.x, v23.y);
        uint2 pk = make_uint2(*(uint32_t*)&h0, *(uint32_t*)&h1);
        *(uint2*)&As[i][j] = pk;
    }
    __syncthreads();

    // MMA: acc[mt][nt] = rows [16mt,16mt+16) x cols [16w+8nt,+8), K=128
    float acc[4][2][4];
#pragma unroll
    for (int mt = 0; mt < 4; ++mt)
#pragma unroll
        for (int nt = 0; nt < 2; ++nt) {
            acc[mt][nt][0] = 0.f; acc[mt][nt][1] = 0.f;
            acc[mt][nt][2] = 0.f; acc[mt][nt][3] = 0.f;
        }

#pragma unroll
    for (int kc = 0; kc < 8; ++kc) {
        int k0 = kc * 16 + (ln & 3) * 2;
#pragma unroll
        for (int mt = 0; mt < 4; ++mt) {
            int rr = mt * 16 + (ln >> 2);
            uint32_t a[4];
            a[0] = *(const uint32_t*)&As[rr][k0];
            a[1] = *(const uint32_t*)&As[rr + 8][k0];
            a[2] = *(const uint32_t*)&As[rr][k0 + 8];
            a[3] = *(const uint32_t*)&As[rr + 8][k0 + 8];
#pragma unroll
            for (int nt = 0; nt < 2; ++nt)
                mma16(acc[mt][nt], a, breg[nt][kc]);
        }
    }
    __syncthreads();  // As reads done; buf becomes Ms

    // stage m = silu(acc + b2) into Ms
    int c0 = (ln & 3) * 2;
#pragma unroll
    for (int mt = 0; mt < 4; ++mt) {
#pragma unroll
        for (int h8 = 0; h8 < 2; ++h8) {
            int rowi = mt * 16 + (ln >> 2) + h8 * 8;
#pragma unroll
            for (int nt = 0; nt < 2; ++nt) {
                int col = warp * 16 + nt * 8 + c0;
                float2 v = silu2_f(acc[mt][nt][h8 * 2 + 0] + b2s[col],
                                   acc[mt][nt][h8 * 2 + 1] + b2s[col + 1]);
                *(float2*)&Ms[rowi][col] = v;
            }
        }
    }
    __syncthreads();

    // segmented reduction scatter: warp w walks rows [8w, 8w+8); lane = col
    // group (4 cols). Receivers are sorted -> runs merge into one float4
    // atomic per receiver-run per warp.
    {
        float4 a4 = make_float4(0.f, 0.f, 0.f, 0.f);
        int prev = -1;
#pragma unroll
        for (int i = 0; i < 8; ++i) {
            int row = warp * 8 + i;
            int r = r_sh[row];
            if (r != prev) {
                if (prev >= 0)
                    atomicAdd((float4*)(g_agg + (size_t)prev * 128 + ln * 4), a4);
                a4 = make_float4(0.f, 0.f, 0.f, 0.f);
                prev = r;
            }
            if (r >= 0) {
                float4 v = *(const float4*)&Ms[row][ln * 4];
                a4.x += v.x; a4.y += v.y; a4.z += v.z; a4.w += v.w;
            }
        }
        if (prev >= 0)
            atomicAdd((float4*)(g_agg + (size_t)prev * 128 + ln * 4), a4);
    }
}

// ============================================================================
// Host launch: kernel launches ONLY (graph-capture safe).
// ============================================================================
extern "C" void kernel_launch(void* const* d_in, const int* in_sizes, int n_in,
                              void* d_out, int out_size)
{
    const float* h_ptr  = (const float*)d_in[0];
    const float* coords = (const float*)d_in[1];
    const int*   ei     = (const int*)d_in[2];   // int32 (JAX downcasts int64)
    const float* W1     = (const float*)d_in[3];
    const float* b1     = (const float*)d_in[4];
    const float* W2     = (const float*)d_in[5];
    const float* b2     = (const float*)d_in[6];
    const float* U1     = (const float*)d_in[7];
    const float* c1     = (const float*)d_in[8];
    const float* U2     = (const float*)d_in[9];
    const float* c2     = (const float*)d_in[10];

    int N = in_sizes[0] / 128;
    int E = in_sizes[2] / 2;
    int mt = (N + 127) / 128;
    int n4 = N * 32;  // N*128/4

    // sort prep (overlappable with node GEMMs by the scheduler)
    zero_scratch<<<(n4 + 255) / 256, 256>>>(N, n4);
    hist_kernel<<<(E + 255) / 256, 256>>>(ei, E);
    scan_kernel<<<1, 1024>>>(N);
    scatter_kernel<<<(E + 255) / 256, 256>>>(ei, E);

    // P = h @ W1[:, :128]^T ; Q = h @ W1[:, 128:256]^T  (W1 row stride 257)
    gemm_node<<<mt, 256>>>(h_ptr, 0, W1, 257, 0, nullptr, 0,
                           nullptr, nullptr, nullptr, 1, N, 0);
    gemm_node<<<mt, 256>>>(h_ptr, 0, W1 + 128, 257, 0, nullptr, 0,
                           nullptr, nullptr, nullptr, 2, N, 0);

    edge_kernel<<<(E + 63) / 64, 256>>>(coords, W1, b1, W2, b2, E);

    // u1 = silu(h @ U1a^T + agg @ U1b^T + c1)
    gemm_node<<<mt, 256>>>(h_ptr, 0, U1, 256, 3, U1 + 128, 256,
                           c1, nullptr, nullptr, 4, N, 1);
    // out = h + u1 @ U2^T + c2
    gemm_node<<<mt, 256>>>(nullptr, 4, U2, 128, 0, nullptr, 0,
                           c2, h_ptr, (float*)d_out, 0, N, 2);
}

// round 13
// speedup vs baseline: 1.1487x; 1.1487x over previous
#include <cuda_runtime.h>
#include <cuda_fp16.h>
#include <cstdint>
#include <cstddef>

// ============================================================================
// EGNN layer: h' = h + MLP_u([h, scatter_add(MLP_m([h_s, h_r, dist]))])
//
// Layer-1 of the edge MLP is linear in gathered features -> node-level GEMMs
// P = h@W1a^T, Q = h@W1b^T, stored in FP16 (halves edge-kernel gather
// traffic). Edge kernel: half gather -> half2 layer-1 + silu -> fp16 MMA
// (W2 in registers) -> silu -> staged float4 atomic scatter (best-known v2).
// ============================================================================

#define DD 128
#define NMAX 50176  // >= N = 50000

__device__ __align__(16) __half g_Ph[(size_t)NMAX * DD];
__device__ __align__(16) __half g_Qh[(size_t)NMAX * DD];
__device__ __align__(16) float  g_agg[(size_t)NMAX * DD];
__device__ __align__(16) float  g_u1[(size_t)NMAX * DD];

__device__ __forceinline__ float* resolve_buf(int code, const float* ext) {
    switch (code) {
        case 1: return (float*)g_Ph;   // fp16 payload, cast at use
        case 2: return (float*)g_Qh;   // fp16 payload, cast at use
        case 3: return g_agg;
        case 4: return g_u1;
        default: return (float*)ext;
    }
}

// silu(x) = 0.5x(1 + tanh(x/2)) -- single MUFU
__device__ __forceinline__ float silu_f(float x) {
    float t;
    asm("tanh.approx.f32 %0, %1;" : "=f"(t) : "f"(0.5f * x));
    return 0.5f * x * (1.f + t);
}
__device__ __forceinline__ float2 silu2_f(float x0, float x1) {
    __half2 ph = __floats2half2_rn(0.5f * x0, 0.5f * x1);
    uint32_t pu = *(uint32_t*)&ph, tu;
    asm("tanh.approx.f16x2 %0, %1;" : "=r"(tu) : "r"(pu));
    float2 tf = __half22float2(*(__half2*)&tu);
    return make_float2(0.5f * x0 * (1.f + tf.x), 0.5f * x1 * (1.f + tf.y));
}
// half2 silu: hx = 0.5x; silu = hx * (1 + tanh(hx))
__device__ __forceinline__ __half2 silu_h2(__half2 x) {
    __half2 hx = __hmul2(x, __float2half2_rn(0.5f));
    uint32_t hu = *(uint32_t*)&hx, tu;
    asm("tanh.approx.f16x2 %0, %1;" : "=r"(tu) : "r"(hu));
    __half2 th = *(__half2*)&tu;
    return __hmul2(hx, __hadd2(__float2half2_rn(1.f), th));
}
__device__ __forceinline__ float tf32r(float x) {
    uint32_t u;
    asm("cvt.rna.tf32.f32 %0, %1;" : "=r"(u) : "f"(x));
    return __uint_as_float(u);
}
__device__ __forceinline__ void mma8(float* c, const uint32_t* a, const uint32_t* b) {
    asm volatile(
        "mma.sync.aligned.m16n8k8.row.col.f32.tf32.tf32.f32 "
        "{%0,%1,%2,%3},{%4,%5,%6,%7},{%8,%9},{%0,%1,%2,%3};\n"
        : "+f"(c[0]), "+f"(c[1]), "+f"(c[2]), "+f"(c[3])
        : "r"(a[0]), "r"(a[1]), "r"(a[2]), "r"(a[3]), "r"(b[0]), "r"(b[1]));
}
__device__ __forceinline__ void mma16(float* c, const uint32_t* a, const uint32_t* b) {
    asm volatile(
        "mma.sync.aligned.m16n8k16.row.col.f32.f16.f16.f32 "
        "{%0,%1,%2,%3},{%4,%5,%6,%7},{%8,%9},{%0,%1,%2,%3};\n"
        : "+f"(c[0]), "+f"(c[1]), "+f"(c[2]), "+f"(c[3])
        : "r"(a[0]), "r"(a[1]), "r"(a[2]), "r"(a[3]), "r"(b[0]), "r"(b[1]));
}

// ============================================================================
// Node-level GEMM (tf32): out[M,128] = epi( sum_p A_p[M,128] @ B_p^T )
// mode 0: raw fp32; 1: silu(acc+bias); 2: acc+bias+resid; 3: raw fp16 out.
// ============================================================================
__global__ __launch_bounds__(256) void gemm_node(
    const float* __restrict__ A0e, int a0c,
    const float* __restrict__ B0, int ldb0,
    int a1c, const float* __restrict__ B1, int ldb1,
    const float* __restrict__ bias, const float* __restrict__ resid,
    float* __restrict__ oute, int outc, int M, int mode)
{
    __shared__ float As[128][36];
    __shared__ float Bs[128][36];
    int tid = threadIdx.x;
    int warp = tid >> 5, ln = tid & 31;
    int m0 = blockIdx.x * 128;

    const float* A0 = resolve_buf(a0c, A0e);
    const float* A1 = (a1c == 0) ? nullptr : resolve_buf(a1c, nullptr);
    float* out = resolve_buf(outc, oute);

    float acc[16][4];
#pragma unroll
    for (int i = 0; i < 16; ++i) {
        acc[i][0] = 0.f; acc[i][1] = 0.f; acc[i][2] = 0.f; acc[i][3] = 0.f;
    }

    for (int p = 0; p < 2; ++p) {
        const float* A = p ? A1 : A0;
        const float* B = p ? B1 : B0;
        int ldb = p ? ldb1 : ldb0;
        if (!A) continue;
        for (int k0 = 0; k0 < 128; k0 += 32) {
#pragma unroll
            for (int i = 0; i < 4; ++i) {
                int r = (tid >> 3) + i * 32;
                int c = (tid & 7) * 4;
                float4 v = make_float4(0.f, 0.f, 0.f, 0.f);
                int gr = m0 + r;
                if (gr < M) v = *(const float4*)(A + (size_t)gr * 128 + k0 + c);
                v.x = tf32r(v.x); v.y = tf32r(v.y); v.z = tf32r(v.z); v.w = tf32r(v.w);
                *(float4*)&As[r][c] = v;
            }
#pragma unroll
            for (int i = 0; i < 4; ++i) {
                int n = (tid >> 3) + i * 32;
                int c = (tid & 7) * 4;
                const float* bp = B + (size_t)n * ldb + k0 + c;
                Bs[n][c + 0] = tf32r(bp[0]);
                Bs[n][c + 1] = tf32r(bp[1]);
                Bs[n][c + 2] = tf32r(bp[2]);
                Bs[n][c + 3] = tf32r(bp[3]);
            }
            __syncthreads();

            int srow = warp * 16 + (ln >> 2);
            int scol = ln & 3;
#pragma unroll
            for (int kk = 0; kk < 4; ++kk) {
                uint32_t a[4];
                a[0] = __float_as_uint(As[srow][kk * 8 + scol]);
                a[1] = __float_as_uint(As[srow + 8][kk * 8 + scol]);
                a[2] = __float_as_uint(As[srow][kk * 8 + scol + 4]);
                a[3] = __float_as_uint(As[srow + 8][kk * 8 + scol + 4]);
#pragma unroll
                for (int nt = 0; nt < 16; ++nt) {
                    uint32_t b[2];
                    b[0] = __float_as_uint(Bs[nt * 8 + (ln >> 2)][kk * 8 + scol]);
                    b[1] = __float_as_uint(Bs[nt * 8 + (ln >> 2)][kk * 8 + scol + 4]);
                    mma8(acc[nt], a, b);
                }
            }
            __syncthreads();
        }
    }

    int r0 = m0 + warp * 16 + (ln >> 2);
    int c0 = (ln & 3) * 2;
#pragma unroll
    for (int nt = 0; nt < 16; ++nt) {
        int col = nt * 8 + c0;
#pragma unroll
        for (int h8 = 0; h8 < 2; ++h8) {
            int row = r0 + h8 * 8;
            if (row >= M) continue;
            float v0 = acc[nt][h8 * 2 + 0];
            float v1 = acc[nt][h8 * 2 + 1];
            if (mode == 3) {
                // fp16 output (P/Q buffers)
                __half2 hv = __floats2half2_rn(v0, v1);
                *(__half2*)((__half*)out + (size_t)row * 128 + col) = hv;
            } else {
                if (mode == 1) {
                    v0 = silu_f(v0 + bias[col]);
                    v1 = silu_f(v1 + bias[col + 1]);
                } else if (mode == 2) {
                    v0 = v0 + bias[col]     + resid[(size_t)row * 128 + col];
                    v1 = v1 + bias[col + 1] + resid[(size_t)row * 128 + col + 1];
                }
                out[(size_t)row * 128 + col]     = v0;
                out[(size_t)row * 128 + col + 1] = v1;
            }
        }
    }
}

// ============================================================================
// Edge kernel (v2 structure, fp16 gathers): 64 edges/block, 256 threads,
// warp w covers cols [16w,16w+16), fp16 MMA m16n8k16.
//   a = silu_h2(P[s]+Q[r]+d*w1c+b1)  (all half2)  -> As[64][136]
//   m = silu(a @ W2^T + b2)  -> Ms (buf reused)  -> float4 atomic scatter
// ============================================================================
#define AS_LD 136   // half stride
#define MS_LD 132   // float stride

__global__ __launch_bounds__(256) void edge_kernel(
    const float* __restrict__ coords,
    const int* __restrict__ ei,     // int32 (JAX downcasts int64)
    const float* __restrict__ W1, const float* __restrict__ b1,
    const float* __restrict__ W2, const float* __restrict__ b2,
    int E)
{
    __shared__ __align__(16) char buf[64 * MS_LD * 4];  // 33792 B, aliased
    __shared__ int     s_sh[64];
    __shared__ int     r_sh[64];
    __shared__ float   dist_sh[64];
    __shared__ __half2 b1h[64];
    __shared__ __half2 w1ch[64];
    __shared__ float   b2s[128];

    half  (*As)[AS_LD] = (half(*)[AS_LD])buf;
    float (*Ms)[MS_LD] = (float(*)[MS_LD])buf;

    int tid = threadIdx.x;
    int warp = tid >> 5, ln = tid & 31;
    int e0 = blockIdx.x * 64;

    // meta
    if (tid < 64) {
        int e = e0 + tid;
        int s = 0, r = -1;
        float d = 0.f;
        if (e < E) {
            s = ei[e];
            r = ei[(size_t)E + e];
            float dx = coords[s * 3 + 0] - coords[r * 3 + 0];
            float dy = coords[s * 3 + 1] - coords[r * 3 + 1];
            float dz = coords[s * 3 + 2] - coords[r * 3 + 2];
            d = sqrtf(dx * dx + dy * dy + dz * dz);
        }
        s_sh[tid] = s; r_sh[tid] = r; dist_sh[tid] = d;
        b1h[tid]  = __floats2half2_rn(b1[2 * tid], b1[2 * tid + 1]);
        w1ch[tid] = __floats2half2_rn(W1[(size_t)(2 * tid) * 257 + 256],
                                      W1[(size_t)(2 * tid + 1) * 257 + 256]);
    }
    if (tid < 128) b2s[tid] = b2[tid];

    // W2 -> per-warp fp16 register fragments. warp w owns cols [16w,16w+16).
    uint32_t breg[2][8][2];
#pragma unroll
    for (int nt = 0; nt < 2; ++nt) {
        int n = warp * 16 + nt * 8 + (ln >> 2);
#pragma unroll
        for (int kc = 0; kc < 8; ++kc) {
            int k0 = kc * 16 + (ln & 3) * 2;
            float2 lo = *(const float2*)(W2 + (size_t)n * 128 + k0);
            float2 hi = *(const float2*)(W2 + (size_t)n * 128 + k0 + 8);
            __half2 hlo = __floats2half2_rn(lo.x, lo.y);
            __half2 hhi = __floats2half2_rn(hi.x, hi.y);
            breg[nt][kc][0] = *(uint32_t*)&hlo;
            breg[nt][kc][1] = *(uint32_t*)&hhi;
        }
    }
    __syncthreads();

    // gather (fp16) + layer-1 (half2) + silu -> As
#pragma unroll
    for (int it = 0; it < 8; ++it) {
        int idx = tid + it * 256;
        int i = idx >> 5;
        int j = (idx & 31) * 4;          // half index, multiple of 4
        int s = s_sh[i], r = r_sh[i];
        uint2 pk = make_uint2(0u, 0u);
        if (r >= 0) {
            __half2 d2 = __float2half2_rn(dist_sh[i]);
            uint2 pv = *(const uint2*)(g_Ph + (size_t)s * 128 + j);
            uint2 qv = *(const uint2*)(g_Qh + (size_t)r * 128 + j);
            __half2 p0 = *(__half2*)&pv.x, p1 = *(__half2*)&pv.y;
            __half2 q0 = *(__half2*)&qv.x, q1 = *(__half2*)&qv.y;
            int jh = j >> 1;
            __half2 x0 = __hadd2(__hadd2(p0, q0), b1h[jh]);
            x0 = __hfma2(d2, w1ch[jh], x0);
            __half2 x1 = __hadd2(__hadd2(p1, q1), b1h[jh + 1]);
            x1 = __hfma2(d2, w1ch[jh + 1], x1);
            __half2 a0 = silu_h2(x0);
            __half2 a1 = silu_h2(x1);
            pk = make_uint2(*(uint32_t*)&a0, *(uint32_t*)&a1);
        }
        *(uint2*)&As[i][j] = pk;
    }
    __syncthreads();

    // MMA: acc[mt][nt] = rows [16mt,16mt+16) x cols [16w+8nt,+8), K=128
    float acc[4][2][4];
#pragma unroll
    for (int mt = 0; mt < 4; ++mt)
#pragma unroll
        for (int nt = 0; nt < 2; ++nt) {
            acc[mt][nt][0] = 0.f; acc[mt][nt][1] = 0.f;
            acc[mt][nt][2] = 0.f; acc[mt][nt][3] = 0.f;
        }

#pragma unroll
    for (int kc = 0; kc < 8; ++kc) {
        int k0 = kc * 16 + (ln & 3) * 2;
#pragma unroll
        for (int mt = 0; mt < 4; ++mt) {
            int rr = mt * 16 + (ln >> 2);
            uint32_t a[4];
            a[0] = *(const uint32_t*)&As[rr][k0];
            a[1] = *(const uint32_t*)&As[rr + 8][k0];
            a[2] = *(const uint32_t*)&As[rr][k0 + 8];
            a[3] = *(const uint32_t*)&As[rr + 8][k0 + 8];
#pragma unroll
            for (int nt = 0; nt < 2; ++nt)
                mma16(acc[mt][nt], a, breg[nt][kc]);
        }
    }
    __syncthreads();  // As reads done; buf becomes Ms

    // stage m = silu(acc + b2) into Ms
    int c0 = (ln & 3) * 2;
#pragma unroll
    for (int mt = 0; mt < 4; ++mt) {
#pragma unroll
        for (int h8 = 0; h8 < 2; ++h8) {
            int rowi = mt * 16 + (ln >> 2) + h8 * 8;
#pragma unroll
            for (int nt = 0; nt < 2; ++nt) {
                int col = warp * 16 + nt * 8 + c0;
                float2 v = silu2_f(acc[mt][nt][h8 * 2 + 0] + b2s[col],
                                   acc[mt][nt][h8 * 2 + 1] + b2s[col + 1]);
                *(float2*)&Ms[rowi][col] = v;
            }
        }
    }
    __syncthreads();

    // scatter: warp w -> rows [8w, 8w+8), float4 vector atomics (coalesced)
#pragma unroll
    for (int rr = 0; rr < 8; ++rr) {
        int row = warp * 8 + rr;
        int r = r_sh[row];
        if (r < 0) continue;
        float4 v = *(const float4*)&Ms[row][ln * 4];
        atomicAdd((float4*)(g_agg + (size_t)r * 128 + ln * 4), v);
    }
}

__global__ void zero_agg(int n4) {
    int i = blockIdx.x * 256 + threadIdx.x;
    if (i < n4) ((float4*)g_agg)[i] = make_float4(0.f, 0.f, 0.f, 0.f);
}

// ============================================================================
// Host launch: kernel launches ONLY (graph-capture safe).
// ============================================================================
extern "C" void kernel_launch(void* const* d_in, const int* in_sizes, int n_in,
                              void* d_out, int out_size)
{
    const float* h_ptr  = (const float*)d_in[0];
    const float* coords = (const float*)d_in[1];
    const int*   ei     = (const int*)d_in[2];   // int32 (JAX downcasts int64)
    const float* W1     = (const float*)d_in[3];
    const float* b1     = (const float*)d_in[4];
    const float* W2     = (const float*)d_in[5];
    const float* b2     = (const float*)d_in[6];
    const float* U1     = (const float*)d_in[7];
    const float* c1     = (const float*)d_in[8];
    const float* U2     = (const float*)d_in[9];
    const float* c2     = (const float*)d_in[10];

    int N = in_sizes[0] / 128;
    int E = in_sizes[2] / 2;
    int mt = (N + 127) / 128;

    // P = h @ W1[:, :128]^T ; Q = h @ W1[:, 128:256]^T  -> fp16 buffers
    gemm_node<<<mt, 256>>>(h_ptr, 0, W1, 257, 0, nullptr, 0,
                           nullptr, nullptr, nullptr, 1, N, 3);
    gemm_node<<<mt, 256>>>(h_ptr, 0, W1 + 128, 257, 0, nullptr, 0,
                           nullptr, nullptr, nullptr, 2, N, 3);

    int n4 = N * 32;  // N*128/4
    zero_agg<<<(n4 + 255) / 256, 256>>>(n4);

    edge_kernel<<<(E + 63) / 64, 256>>>(coords, ei, W1, b1, W2, b2, E);

    // u1 = silu(h @ U1a^T + agg @ U1b^T + c1)
    gemm_node<<<mt, 256>>>(h_ptr, 0, U1, 256, 3, U1 + 128, 256,
                           c1, nullptr, nullptr, 4, N, 1);
    // out = h + u1 @ U2^T + c2
    gemm_node<<<mt, 256>>>(nullptr, 4, U2, 128, 0, nullptr, 0,
                           c2, h_ptr, (float*)d_out, 0, N, 2);
}

// round 14
// speedup vs baseline: 1.1611x; 1.0108x over previous
#include <cuda_runtime.h>
#include <cuda_fp16.h>
#include <cstdint>
#include <cstddef>

// ============================================================================
// EGNN layer: h' = h + MLP_u([h, scatter_add(MLP_m([h_s, h_r, dist]))])
//
// Layer-1 of the edge MLP is linear in gathered features -> node-level GEMMs
// P = h@W1a^T, Q = h@W1b^T, stored FP16. Edge kernel: half gather -> half2
// layer-1 + silu -> fp16 MMA (A via ldmatrix.x4, W2 in registers) -> silu
// -> fp16 staged tile -> float4 atomic scatter.
// ============================================================================

#define DD 128
#define NMAX 50176  // >= N = 50000

__device__ __align__(16) __half g_Ph[(size_t)NMAX * DD];
__device__ __align__(16) __half g_Qh[(size_t)NMAX * DD];
__device__ __align__(16) float  g_agg[(size_t)NMAX * DD];
__device__ __align__(16) float  g_u1[(size_t)NMAX * DD];

__device__ __forceinline__ float* resolve_buf(int code, const float* ext) {
    switch (code) {
        case 1: return (float*)g_Ph;   // fp16 payload, cast at use
        case 2: return (float*)g_Qh;   // fp16 payload, cast at use
        case 3: return g_agg;
        case 4: return g_u1;
        default: return (float*)ext;
    }
}

// silu(x) = 0.5x(1 + tanh(x/2)) -- single MUFU
__device__ __forceinline__ float silu_f(float x) {
    float t;
    asm("tanh.approx.f32 %0, %1;" : "=f"(t) : "f"(0.5f * x));
    return 0.5f * x * (1.f + t);
}
__device__ __forceinline__ float2 silu2_f(float x0, float x1) {
    __half2 ph = __floats2half2_rn(0.5f * x0, 0.5f * x1);
    uint32_t pu = *(uint32_t*)&ph, tu;
    asm("tanh.approx.f16x2 %0, %1;" : "=r"(tu) : "r"(pu));
    float2 tf = __half22float2(*(__half2*)&tu);
    return make_float2(0.5f * x0 * (1.f + tf.x), 0.5f * x1 * (1.f + tf.y));
}
__device__ __forceinline__ __half2 silu_h2(__half2 x) {
    __half2 hx = __hmul2(x, __float2half2_rn(0.5f));
    uint32_t hu = *(uint32_t*)&hx, tu;
    asm("tanh.approx.f16x2 %0, %1;" : "=r"(tu) : "r"(hu));
    __half2 th = *(__half2*)&tu;
    return __hmul2(hx, __hadd2(__float2half2_rn(1.f), th));
}
__device__ __forceinline__ float tf32r(float x) {
    uint32_t u;
    asm("cvt.rna.tf32.f32 %0, %1;" : "=r"(u) : "f"(x));
    return __uint_as_float(u);
}
__device__ __forceinline__ void mma8(float* c, const uint32_t* a, const uint32_t* b) {
    asm volatile(
        "mma.sync.aligned.m16n8k8.row.col.f32.tf32.tf32.f32 "
        "{%0,%1,%2,%3},{%4,%5,%6,%7},{%8,%9},{%0,%1,%2,%3};\n"
        : "+f"(c[0]), "+f"(c[1]), "+f"(c[2]), "+f"(c[3])
        : "r"(a[0]), "r"(a[1]), "r"(a[2]), "r"(a[3]), "r"(b[0]), "r"(b[1]));
}
__device__ __forceinline__ void mma16(float* c, const uint32_t* a, const uint32_t* b) {
    asm volatile(
        "mma.sync.aligned.m16n8k16.row.col.f32.f16.f16.f32 "
        "{%0,%1,%2,%3},{%4,%5,%6,%7},{%8,%9},{%0,%1,%2,%3};\n"
        : "+f"(c[0]), "+f"(c[1]), "+f"(c[2]), "+f"(c[3])
        : "r"(a[0]), "r"(a[1]), "r"(a[2]), "r"(a[3]), "r"(b[0]), "r"(b[1]));
}

// ============================================================================
// Node-level GEMM (tf32): out[M,128] = epi( sum_p A_p[M,128] @ B_p^T )
// mode 0: raw fp32; 1: silu(acc+bias); 2: acc+bias+resid; 3: raw fp16 out.
// ============================================================================
__global__ __launch_bounds__(256) void gemm_node(
    const float* __restrict__ A0e, int a0c,
    const float* __restrict__ B0, int ldb0,
    int a1c, const float* __restrict__ B1, int ldb1,
    const float* __restrict__ bias, const float* __restrict__ resid,
    float* __restrict__ oute, int outc, int M, int mode)
{
    __shared__ float As[128][36];
    __shared__ float Bs[128][36];
    int tid = threadIdx.x;
    int warp = tid >> 5, ln = tid & 31;
    int m0 = blockIdx.x * 128;

    const float* A0 = resolve_buf(a0c, A0e);
    const float* A1 = (a1c == 0) ? nullptr : resolve_buf(a1c, nullptr);
    float* out = resolve_buf(outc, oute);

    float acc[16][4];
#pragma unroll
    for (int i = 0; i < 16; ++i) {
        acc[i][0] = 0.f; acc[i][1] = 0.f; acc[i][2] = 0.f; acc[i][3] = 0.f;
    }

    for (int p = 0; p < 2; ++p) {
        const float* A = p ? A1 : A0;
        const float* B = p ? B1 : B0;
        int ldb = p ? ldb1 : ldb0;
        if (!A) continue;
        for (int k0 = 0; k0 < 128; k0 += 32) {
#pragma unroll
            for (int i = 0; i < 4; ++i) {
                int r = (tid >> 3) + i * 32;
                int c = (tid & 7) * 4;
                float4 v = make_float4(0.f, 0.f, 0.f, 0.f);
                int gr = m0 + r;
                if (gr < M) v = *(const float4*)(A + (size_t)gr * 128 + k0 + c);
                v.x = tf32r(v.x); v.y = tf32r(v.y); v.z = tf32r(v.z); v.w = tf32r(v.w);
                *(float4*)&As[r][c] = v;
            }
#pragma unroll
            for (int i = 0; i < 4; ++i) {
                int n = (tid >> 3) + i * 32;
                int c = (tid & 7) * 4;
                const float* bp = B + (size_t)n * ldb + k0 + c;
                Bs[n][c + 0] = tf32r(bp[0]);
                Bs[n][c + 1] = tf32r(bp[1]);
                Bs[n][c + 2] = tf32r(bp[2]);
                Bs[n][c + 3] = tf32r(bp[3]);
            }
            __syncthreads();

            int srow = warp * 16 + (ln >> 2);
            int scol = ln & 3;
#pragma unroll
            for (int kk = 0; kk < 4; ++kk) {
                uint32_t a[4];
                a[0] = __float_as_uint(As[srow][kk * 8 + scol]);
                a[1] = __float_as_uint(As[srow + 8][kk * 8 + scol]);
                a[2] = __float_as_uint(As[srow][kk * 8 + scol + 4]);
                a[3] = __float_as_uint(As[srow + 8][kk * 8 + scol + 4]);
#pragma unroll
                for (int nt = 0; nt < 16; ++nt) {
                    uint32_t b[2];
                    b[0] = __float_as_uint(Bs[nt * 8 + (ln >> 2)][kk * 8 + scol]);
                    b[1] = __float_as_uint(Bs[nt * 8 + (ln >> 2)][kk * 8 + scol + 4]);
                    mma8(acc[nt], a, b);
                }
            }
            __syncthreads();
        }
    }

    int r0 = m0 + warp * 16 + (ln >> 2);
    int c0 = (ln & 3) * 2;
#pragma unroll
    for (int nt = 0; nt < 16; ++nt) {
        int col = nt * 8 + c0;
#pragma unroll
        for (int h8 = 0; h8 < 2; ++h8) {
            int row = r0 + h8 * 8;
            if (row >= M) continue;
            float v0 = acc[nt][h8 * 2 + 0];
            float v1 = acc[nt][h8 * 2 + 1];
            if (mode == 3) {
                __half2 hv = __floats2half2_rn(v0, v1);
                *(__half2*)((__half*)out + (size_t)row * 128 + col) = hv;
            } else {
                if (mode == 1) {
                    v0 = silu_f(v0 + bias[col]);
                    v1 = silu_f(v1 + bias[col + 1]);
                } else if (mode == 2) {
                    v0 = v0 + bias[col]     + resid[(size_t)row * 128 + col];
                    v1 = v1 + bias[col + 1] + resid[(size_t)row * 128 + col + 1];
                }
                out[(size_t)row * 128 + col]     = v0;
                out[(size_t)row * 128 + col + 1] = v1;
            }
        }
    }
}

// ============================================================================
// Edge kernel: 64 edges/block, 256 threads, warp w covers cols [16w,16w+16),
// fp16 MMA m16n8k16, A fragments via ldmatrix.x4, Ms staged in fp16.
// ============================================================================
#define AS_LD 136   // half stride: 272B rows; ldmatrix phases conflict-free,
                    // stage-write banks (4g+q) all distinct

__global__ __launch_bounds__(256) void edge_kernel(
    const float* __restrict__ coords,
    const int* __restrict__ ei,     // int32 (JAX downcasts int64)
    const float* __restrict__ W1, const float* __restrict__ b1,
    const float* __restrict__ W2, const float* __restrict__ b2,
    int E)
{
    __shared__ __align__(16) char buf[64 * AS_LD * 2];  // 17408 B, aliased
    __shared__ int     s_sh[64];
    __shared__ int     r_sh[64];
    __shared__ float   dist_sh[64];
    __shared__ __half2 b1h[64];
    __shared__ __half2 w1ch[64];
    __shared__ float   b2s[128];

    half (*As)[AS_LD]  = (half(*)[AS_LD])buf;
    half (*Msh)[AS_LD] = (half(*)[AS_LD])buf;   // reused after MMA

    int tid = threadIdx.x;
    int warp = tid >> 5, ln = tid & 31;
    int e0 = blockIdx.x * 64;

    // meta
    if (tid < 64) {
        int e = e0 + tid;
        int s = 0, r = -1;
        float d = 0.f;
        if (e < E) {
            s = ei[e];
            r = ei[(size_t)E + e];
            float dx = coords[s * 3 + 0] - coords[r * 3 + 0];
            float dy = coords[s * 3 + 1] - coords[r * 3 + 1];
            float dz = coords[s * 3 + 2] - coords[r * 3 + 2];
            d = sqrtf(dx * dx + dy * dy + dz * dz);
        }
        s_sh[tid] = s; r_sh[tid] = r; dist_sh[tid] = d;
        b1h[tid]  = __floats2half2_rn(b1[2 * tid], b1[2 * tid + 1]);
        w1ch[tid] = __floats2half2_rn(W1[(size_t)(2 * tid) * 257 + 256],
                                      W1[(size_t)(2 * tid + 1) * 257 + 256]);
    }
    if (tid < 128) b2s[tid] = b2[tid];

    // W2 -> per-warp fp16 register fragments. warp w owns cols [16w,16w+16).
    uint32_t breg[2][8][2];
#pragma unroll
    for (int nt = 0; nt < 2; ++nt) {
        int n = warp * 16 + nt * 8 + (ln >> 2);
#pragma unroll
        for (int kc = 0; kc < 8; ++kc) {
            int k0 = kc * 16 + (ln & 3) * 2;
            float2 lo = *(const float2*)(W2 + (size_t)n * 128 + k0);
            float2 hi = *(const float2*)(W2 + (size_t)n * 128 + k0 + 8);
            __half2 hlo = __floats2half2_rn(lo.x, lo.y);
            __half2 hhi = __floats2half2_rn(hi.x, hi.y);
            breg[nt][kc][0] = *(uint32_t*)&hlo;
            breg[nt][kc][1] = *(uint32_t*)&hhi;
        }
    }
    __syncthreads();

    // gather (fp16) + layer-1 (half2) + silu -> As
#pragma unroll
    for (int it = 0; it < 8; ++it) {
        int idx = tid + it * 256;
        int i = idx >> 5;
        int j = (idx & 31) * 4;          // half index, multiple of 4
        int s = s_sh[i], r = r_sh[i];
        uint2 pk = make_uint2(0u, 0u);
        if (r >= 0) {
            __half2 d2 = __float2half2_rn(dist_sh[i]);
            uint2 pv = *(const uint2*)(g_Ph + (size_t)s * 128 + j);
            uint2 qv = *(const uint2*)(g_Qh + (size_t)r * 128 + j);
            __half2 p0 = *(__half2*)&pv.x, p1 = *(__half2*)&pv.y;
            __half2 q0 = *(__half2*)&qv.x, q1 = *(__half2*)&qv.y;
            int jh = j >> 1;
            __half2 x0 = __hadd2(__hadd2(p0, q0), b1h[jh]);
            x0 = __hfma2(d2, w1ch[jh], x0);
            __half2 x1 = __hadd2(__hadd2(p1, q1), b1h[jh + 1]);
            x1 = __hfma2(d2, w1ch[jh + 1], x1);
            __half2 a0 = silu_h2(x0);
            __half2 a1 = silu_h2(x1);
            pk = make_uint2(*(uint32_t*)&a0, *(uint32_t*)&a1);
        }
        *(uint2*)&As[i][j] = pk;
    }
    __syncthreads();

    // MMA: acc[mt][nt] = rows [16mt,16mt+16) x cols [16w+8nt,+8), K=128.
    // A fragments via ldmatrix.x4 (mapping correctness-proven in v3).
    float acc[4][2][4];
#pragma unroll
    for (int mt = 0; mt < 4; ++mt)
#pragma unroll
        for (int nt = 0; nt < 2; ++nt) {
            acc[mt][nt][0] = 0.f; acc[mt][nt][1] = 0.f;
            acc[mt][nt][2] = 0.f; acc[mt][nt][3] = 0.f;
        }

#pragma unroll
    for (int kc = 0; kc < 8; ++kc) {
#pragma unroll
        for (int mt = 0; mt < 4; ++mt) {
            int lrow = mt * 16 + (ln & 15);
            int lcol = kc * 16 + (ln >> 4) * 8;
            uint32_t addr = (uint32_t)__cvta_generic_to_shared(&As[lrow][lcol]);
            uint32_t a[4];
            asm volatile(
                "ldmatrix.sync.aligned.m8n8.x4.shared.b16 {%0,%1,%2,%3}, [%4];"
                : "=r"(a[0]), "=r"(a[1]), "=r"(a[2]), "=r"(a[3])
                : "r"(addr));
#pragma unroll
            for (int nt = 0; nt < 2; ++nt)
                mma16(acc[mt][nt], a, breg[nt][kc]);
        }
    }
    __syncthreads();  // As reads done; buf becomes Msh

    // stage m = silu(acc + b2) into Msh (fp16, one 4B word per value-pair)
    int c0 = (ln & 3) * 2;
#pragma unroll
    for (int mt = 0; mt < 4; ++mt) {
#pragma unroll
        for (int h8 = 0; h8 < 2; ++h8) {
            int rowi = mt * 16 + (ln >> 2) + h8 * 8;
#pragma unroll
            for (int nt = 0; nt < 2; ++nt) {
                int col = warp * 16 + nt * 8 + c0;
                float2 v = silu2_f(acc[mt][nt][h8 * 2 + 0] + b2s[col],
                                   acc[mt][nt][h8 * 2 + 1] + b2s[col + 1]);
                __half2 hv = __floats2half2_rn(v.x, v.y);
                *(__half2*)&Msh[rowi][col] = hv;
            }
        }
    }
    __syncthreads();

    // scatter: warp w -> rows [8w, 8w+8); lane reads 4 halves, converts,
    // one float4 atomic (coalesced, proven-best epilogue)
#pragma unroll
    for (int rr = 0; rr < 8; ++rr) {
        int row = warp * 8 + rr;
        int r = r_sh[row];
        if (r < 0) continue;
        uint2 hw = *(const uint2*)&Msh[row][ln * 4];
        float2 f0 = __half22float2(*(__half2*)&hw.x);
        float2 f1 = __half22float2(*(__half2*)&hw.y);
        float4 v = make_float4(f0.x, f0.y, f1.x, f1.y);
        atomicAdd((float4*)(g_agg + (size_t)r * 128 + ln * 4), v);
    }
}

__global__ void zero_agg(int n4) {
    int i = blockIdx.x * 256 + threadIdx.x;
    if (i < n4) ((float4*)g_agg)[i] = make_float4(0.f, 0.f, 0.f, 0.f);
}

// ============================================================================
// Host launch: kernel launches ONLY (graph-capture safe).
// ============================================================================
extern "C" void kernel_launch(void* const* d_in, const int* in_sizes, int n_in,
                              void* d_out, int out_size)
{
    const float* h_ptr  = (const float*)d_in[0];
    const float* coords = (const float*)d_in[1];
    const int*   ei     = (const int*)d_in[2];   // int32 (JAX downcasts int64)
    const float* W1     = (const float*)d_in[3];
    const float* b1     = (const float*)d_in[4];
    const float* W2     = (const float*)d_in[5];
    const float* b2     = (const float*)d_in[6];
    const float* U1     = (const float*)d_in[7];
    const float* c1     = (const float*)d_in[8];
    const float* U2     = (const float*)d_in[9];
    const float* c2     = (const float*)d_in[10];

    int N = in_sizes[0] / 128;
    int E = in_sizes[2] / 2;
    int mt = (N + 127) / 128;

    // P = h @ W1[:, :128]^T ; Q = h @ W1[:, 128:256]^T  -> fp16 buffers
    gemm_node<<<mt, 256>>>(h_ptr, 0, W1, 257, 0, nullptr, 0,
                           nullptr, nullptr, nullptr, 1, N, 3);
    gemm_node<<<mt, 256>>>(h_ptr, 0, W1 + 128, 257, 0, nullptr, 0,
                           nullptr, nullptr, nullptr, 2, N, 3);

    int n4 = N * 32;  // N*128/4
    zero_agg<<<(n4 + 255) / 256, 256>>>(n4);

    edge_kernel<<<(E + 63) / 64, 256>>>(coords, ei, W1, b1, W2, b2, E);

    // u1 = silu(h @ U1a^T + agg @ U1b^T + c1)
    gemm_node<<<mt, 256>>>(h_ptr, 0, U1, 256, 3, U1 + 128, 256,
                           c1, nullptr, nullptr, 4, N, 1);
    // out = h + u1 @ U2^T + c2
    gemm_node<<<mt, 256>>>(nullptr, 4, U2, 128, 0, nullptr, 0,
                           c2, h_ptr, (float*)d_out, 0, N, 2);
}

// round 16
// speedup vs baseline: 1.3654x; 1.1760x over previous
#include <cuda_runtime.h>
#include <cuda_fp16.h>
#include <cstdint>
#include <cstddef>

// ============================================================================
// EGNN layer: h' = h + MLP_u([h, scatter_add(MLP_m([h_s, h_r, dist]))])
//
// Layer-1 of the edge MLP is linear in gathered features -> node-level GEMMs
// P = h@W1a^T, Q = h@W1b^T, stored FP16. Edge kernel: half gather -> half2
// layer-1 + silu -> fp16 MMA (A via ldmatrix.x4, W2 from PRE-PACKED
// lane-ordered fp16 fragments, coalesced LDG.128) -> silu -> fp16 staged
// tile -> float4 atomic scatter.
// ============================================================================

#define DD 128
#define NMAX 50176  // >= N = 50000

__device__ __align__(16) __half g_Ph[(size_t)NMAX * DD];
__device__ __align__(16) __half g_Qh[(size_t)NMAX * DD];
__device__ __align__(16) float  g_agg[(size_t)NMAX * DD];
__device__ __align__(16) float  g_u1[(size_t)NMAX * DD];
// W2 fp16 B-fragments, lane-ordered: uint4 index = warp*256 + i*32 + lane,
// holding fragment values v = i*4 + {0..3};  v = nt*16 + kc*2 + j.
__device__ uint4 g_W2frag[8 * 8 * 32];

__device__ __forceinline__ float* resolve_buf(int code, const float* ext) {
    switch (code) {
        case 1: return (float*)g_Ph;   // fp16 payload, cast at use
        case 2: return (float*)g_Qh;   // fp16 payload, cast at use
        case 3: return g_agg;
        case 4: return g_u1;
        default: return (float*)ext;
    }
}

// silu(x) = 0.5x(1 + tanh(x/2)) -- single MUFU
__device__ __forceinline__ float silu_f(float x) {
    float t;
    asm("tanh.approx.f32 %0, %1;" : "=f"(t) : "f"(0.5f * x));
    return 0.5f * x * (1.f + t);
}
__device__ __forceinline__ float2 silu2_f(float x0, float x1) {
    __half2 ph = __floats2half2_rn(0.5f * x0, 0.5f * x1);
    uint32_t pu = *(uint32_t*)&ph, tu;
    asm("tanh.approx.f16x2 %0, %1;" : "=r"(tu) : "r"(pu));
    float2 tf = __half22float2(*(__half2*)&tu);
    return make_float2(0.5f * x0 * (1.f + tf.x), 0.5f * x1 * (1.f + tf.y));
}
__device__ __forceinline__ __half2 silu_h2(__half2 x) {
    __half2 hx = __hmul2(x, __float2half2_rn(0.5f));
    uint32_t hu = *(uint32_t*)&hx, tu;
    asm("tanh.approx.f16x2 %0, %1;" : "=r"(tu) : "r"(hu));
    __half2 th = *(__half2*)&tu;
    return __hmul2(hx, __hadd2(__float2half2_rn(1.f), th));
}
__device__ __forceinline__ float tf32r(float x) {
    uint32_t u;
    asm("cvt.rna.tf32.f32 %0, %1;" : "=r"(u) : "f"(x));
    return __uint_as_float(u);
}
__device__ __forceinline__ void mma8(float* c, const uint32_t* a, const uint32_t* b) {
    asm volatile(
        "mma.sync.aligned.m16n8k8.row.col.f32.tf32.tf32.f32 "
        "{%0,%1,%2,%3},{%4,%5,%6,%7},{%8,%9},{%0,%1,%2,%3};\n"
        : "+f"(c[0]), "+f"(c[1]), "+f"(c[2]), "+f"(c[3])
        : "r"(a[0]), "r"(a[1]), "r"(a[2]), "r"(a[3]), "r"(b[0]), "r"(b[1]));
}
__device__ __forceinline__ void mma16(float* c, const uint32_t* a, const uint32_t* b) {
    asm volatile(
        "mma.sync.aligned.m16n8k16.row.col.f32.f16.f16.f32 "
        "{%0,%1,%2,%3},{%4,%5,%6,%7},{%8,%9},{%0,%1,%2,%3};\n"
        : "+f"(c[0]), "+f"(c[1]), "+f"(c[2]), "+f"(c[3])
        : "r"(a[0]), "r"(a[1]), "r"(a[2]), "r"(a[3]), "r"(b[0]), "r"(b[1]));
}

// ============================================================================
// Prep: pack W2 (fp32 [128][128]) into lane-ordered fp16 mma B-fragments.
// Flat u32 index t = w*1024 + i*128 + ln*4 + c  (matches the edge kernel's
// uint4 loads: bflat[i*4+c] <- u32 (w*256 + i*32 + ln)*4 + c).
// Decode: c = t&3, ln = (t>>2)&31, i = (t>>7)&7, w = t>>10.
// v = i*4 + c; nt = v>>4, kc = (v>>1)&7, j = v&1;
// n = w*16 + nt*8 + (ln>>2), kh = kc*16 + (ln&3)*2 + j*8
// value = half2(W2[n][kh], W2[n][kh+1])   (R13-proven fragment layout)
// ============================================================================
__global__ void prep_w2(const float* __restrict__ W2) {
    int t = blockIdx.x * 256 + threadIdx.x;   // 0..8191
    if (t >= 8192) return;
    int c  = t & 3;
    int ln = (t >> 2) & 31;
    int i  = (t >> 7) & 7;
    int w  = t >> 10;
    int v  = i * 4 + c;
    int nt = v >> 4;
    int kc = (v >> 1) & 7;
    int j  = v & 1;
    int n  = w * 16 + nt * 8 + (ln >> 2);
    int kh = kc * 16 + (ln & 3) * 2 + j * 8;
    __half2 h = __floats2half2_rn(W2[(size_t)n * 128 + kh],
                                  W2[(size_t)n * 128 + kh + 1]);
    ((uint32_t*)g_W2frag)[t] = *(uint32_t*)&h;
}

// ============================================================================
// Node-level GEMM (tf32): out[M,128] = epi( sum_p A_p[M,128] @ B_p^T )
// mode 0: raw fp32; 1: silu(acc+bias); 2: acc+bias+resid; 3: raw fp16 out.
// ============================================================================
__global__ __launch_bounds__(256) void gemm_node(
    const float* __restrict__ A0e, int a0c,
    const float* __restrict__ B0, int ldb0,
    int a1c, const float* __restrict__ B1, int ldb1,
    const float* __restrict__ bias, const float* __restrict__ resid,
    float* __restrict__ oute, int outc, int M, int mode)
{
    __shared__ float As[128][36];
    __shared__ float Bs[128][36];
    int tid = threadIdx.x;
    int warp = tid >> 5, ln = tid & 31;
    int m0 = blockIdx.x * 128;

    const float* A0 = resolve_buf(a0c, A0e);
    const float* A1 = (a1c == 0) ? nullptr : resolve_buf(a1c, nullptr);
    float* out = resolve_buf(outc, oute);

    float acc[16][4];
#pragma unroll
    for (int i = 0; i < 16; ++i) {
        acc[i][0] = 0.f; acc[i][1] = 0.f; acc[i][2] = 0.f; acc[i][3] = 0.f;
    }

    for (int p = 0; p < 2; ++p) {
        const float* A = p ? A1 : A0;
        const float* B = p ? B1 : B0;
        int ldb = p ? ldb1 : ldb0;
        if (!A) continue;
        for (int k0 = 0; k0 < 128; k0 += 32) {
#pragma unroll
            for (int i = 0; i < 4; ++i) {
                int r = (tid >> 3) + i * 32;
                int c = (tid & 7) * 4;
                float4 v = make_float4(0.f, 0.f, 0.f, 0.f);
                int gr = m0 + r;
                if (gr < M) v = *(const float4*)(A + (size_t)gr * 128 + k0 + c);
                v.x = tf32r(v.x); v.y = tf32r(v.y); v.z = tf32r(v.z); v.w = tf32r(v.w);
                *(float4*)&As[r][c] = v;
            }
#pragma unroll
            for (int i = 0; i < 4; ++i) {
                int n = (tid >> 3) + i * 32;
                int c = (tid & 7) * 4;
                const float* bp = B + (size_t)n * ldb + k0 + c;
                Bs[n][c + 0] = tf32r(bp[0]);
                Bs[n][c + 1] = tf32r(bp[1]);
                Bs[n][c + 2] = tf32r(bp[2]);
                Bs[n][c + 3] = tf32r(bp[3]);
            }
            __syncthreads();

            int srow = warp * 16 + (ln >> 2);
            int scol = ln & 3;
#pragma unroll
            for (int kk = 0; kk < 4; ++kk) {
                uint32_t a[4];
                a[0] = __float_as_uint(As[srow][kk * 8 + scol]);
                a[1] = __float_as_uint(As[srow + 8][kk * 8 + scol]);
                a[2] = __float_as_uint(As[srow][kk * 8 + scol + 4]);
                a[3] = __float_as_uint(As[srow + 8][kk * 8 + scol + 4]);
#pragma unroll
                for (int nt = 0; nt < 16; ++nt) {
                    uint32_t b[2];
                    b[0] = __float_as_uint(Bs[nt * 8 + (ln >> 2)][kk * 8 + scol]);
                    b[1] = __float_as_uint(Bs[nt * 8 + (ln >> 2)][kk * 8 + scol + 4]);
                    mma8(acc[nt], a, b);
                }
            }
            __syncthreads();
        }
    }

    int r0 = m0 + warp * 16 + (ln >> 2);
    int c0 = (ln & 3) * 2;
#pragma unroll
    for (int nt = 0; nt < 16; ++nt) {
        int col = nt * 8 + c0;
#pragma unroll
        for (int h8 = 0; h8 < 2; ++h8) {
            int row = r0 + h8 * 8;
            if (row >= M) continue;
            float v0 = acc[nt][h8 * 2 + 0];
            float v1 = acc[nt][h8 * 2 + 1];
            if (mode == 3) {
                __half2 hv = __floats2half2_rn(v0, v1);
                *(__half2*)((__half*)out + (size_t)row * 128 + col) = hv;
            } else {
                if (mode == 1) {
                    v0 = silu_f(v0 + bias[col]);
                    v1 = silu_f(v1 + bias[col + 1]);
                } else if (mode == 2) {
                    v0 = v0 + bias[col]     + resid[(size_t)row * 128 + col];
                    v1 = v1 + bias[col + 1] + resid[(size_t)row * 128 + col + 1];
                }
                out[(size_t)row * 128 + col]     = v0;
                out[(size_t)row * 128 + col + 1] = v1;
            }
        }
    }
}

// ============================================================================
// Edge kernel: 64 edges/block, 256 threads, warp w covers cols [16w,16w+16),
// fp16 MMA m16n8k16, A via ldmatrix.x4, W2 from pre-packed fragments,
// Ms staged fp16, float4 atomic scatter.
// ============================================================================
#define AS_LD 136   // half stride: 272B rows; ldmatrix phases conflict-free

__global__ __launch_bounds__(256) void edge_kernel(
    const float* __restrict__ coords,
    const int* __restrict__ ei,     // int32 (JAX downcasts int64)
    const float* __restrict__ W1, const float* __restrict__ b1,
    const float* __restrict__ b2,
    int E)
{
    __shared__ __align__(16) char buf[64 * AS_LD * 2];  // 17408 B, aliased
    __shared__ int     s_sh[64];
    __shared__ int     r_sh[64];
    __shared__ float   dist_sh[64];
    __shared__ __half2 b1h[64];
    __shared__ __half2 w1ch[64];
    __shared__ float   b2s[128];

    half (*As)[AS_LD]  = (half(*)[AS_LD])buf;
    half (*Msh)[AS_LD] = (half(*)[AS_LD])buf;   // reused after MMA

    int tid = threadIdx.x;
    int warp = tid >> 5, ln = tid & 31;
    int e0 = blockIdx.x * 64;

    // W2 fragments: 8 coalesced LDG.128 per warp (L2-resident, 512B/instr)
    uint32_t bflat[32];
    {
        const uint4* bp = g_W2frag + warp * 256 + ln;
#pragma unroll
        for (int i = 0; i < 8; ++i) {
            uint4 t = bp[i * 32];
            bflat[i * 4 + 0] = t.x; bflat[i * 4 + 1] = t.y;
            bflat[i * 4 + 2] = t.z; bflat[i * 4 + 3] = t.w;
        }
    }

    // meta
    if (tid < 64) {
        int e = e0 + tid;
        int s = 0, r = -1;
        float d = 0.f;
        if (e < E) {
            s = ei[e];
            r = ei[(size_t)E + e];
            float dx = coords[s * 3 + 0] - coords[r * 3 + 0];
            float dy = coords[s * 3 + 1] - coords[r * 3 + 1];
            float dz = coords[s * 3 + 2] - coords[r * 3 + 2];
            d = sqrtf(dx * dx + dy * dy + dz * dz);
        }
        s_sh[tid] = s; r_sh[tid] = r; dist_sh[tid] = d;
        b1h[tid]  = __floats2half2_rn(b1[2 * tid], b1[2 * tid + 1]);
        w1ch[tid] = __floats2half2_rn(W1[(size_t)(2 * tid) * 257 + 256],
                                      W1[(size_t)(2 * tid + 1) * 257 + 256]);
    }
    if (tid < 128) b2s[tid] = b2[tid];
    __syncthreads();

    // gather (fp16) + layer-1 (half2) + silu -> As
#pragma unroll
    for (int it = 0; it < 8; ++it) {
        int idx = tid + it * 256;
        int i = idx >> 5;
        int j = (idx & 31) * 4;          // half index, multiple of 4
        int s = s_sh[i], r = r_sh[i];
        uint2 pk = make_uint2(0u, 0u);
        if (r >= 0) {
            __half2 d2 = __float2half2_rn(dist_sh[i]);
            uint2 pv = *(const uint2*)(g_Ph + (size_t)s * 128 + j);
            uint2 qv = *(const uint2*)(g_Qh + (size_t)r * 128 + j);
            __half2 p0 = *(__half2*)&pv.x, p1 = *(__half2*)&pv.y;
            __half2 q0 = *(__half2*)&qv.x, q1 = *(__half2*)&qv.y;
            int jh = j >> 1;
            __half2 x0 = __hadd2(__hadd2(p0, q0), b1h[jh]);
            x0 = __hfma2(d2, w1ch[jh], x0);
            __half2 x1 = __hadd2(__hadd2(p1, q1), b1h[jh + 1]);
            x1 = __hfma2(d2, w1ch[jh + 1], x1);
            __half2 a0 = silu_h2(x0);
            __half2 a1 = silu_h2(x1);
            pk = make_uint2(*(uint32_t*)&a0, *(uint32_t*)&a1);
        }
        *(uint2*)&As[i][j] = pk;
    }
    __syncthreads();

    // MMA: acc[mt][nt] = rows [16mt,16mt+16) x cols [16w+8nt,+8), K=128.
    float acc[4][2][4];
#pragma unroll
    for (int mt = 0; mt < 4; ++mt)
#pragma unroll
        for (int nt = 0; nt < 2; ++nt) {
            acc[mt][nt][0] = 0.f; acc[mt][nt][1] = 0.f;
            acc[mt][nt][2] = 0.f; acc[mt][nt][3] = 0.f;
        }

#pragma unroll
    for (int kc = 0; kc < 8; ++kc) {
#pragma unroll
        for (int mt = 0; mt < 4; ++mt) {
            int lrow = mt * 16 + (ln & 15);
            int lcol = kc * 16 + (ln >> 4) * 8;
            uint32_t addr = (uint32_t)__cvta_generic_to_shared(&As[lrow][lcol]);
            uint32_t a[4];
            asm volatile(
                "ldmatrix.sync.aligned.m8n8.x4.shared.b16 {%0,%1,%2,%3}, [%4];"
                : "=r"(a[0]), "=r"(a[1]), "=r"(a[2]), "=r"(a[3])
                : "r"(addr));
#pragma unroll
            for (int nt = 0; nt < 2; ++nt)
                mma16(acc[mt][nt], a, &bflat[nt * 16 + kc * 2]);
        }
    }
    __syncthreads();  // As reads done; buf becomes Msh

    // stage m = silu(acc + b2) into Msh (fp16)
    int c0 = (ln & 3) * 2;
#pragma unroll
    for (int mt = 0; mt < 4; ++mt) {
#pragma unroll
        for (int h8 = 0; h8 < 2; ++h8) {
            int rowi = mt * 16 + (ln >> 2) + h8 * 8;
#pragma unroll
            for (int nt = 0; nt < 2; ++nt) {
                int col = warp * 16 + nt * 8 + c0;
                float2 v = silu2_f(acc[mt][nt][h8 * 2 + 0] + b2s[col],
                                   acc[mt][nt][h8 * 2 + 1] + b2s[col + 1]);
                __half2 hv = __floats2half2_rn(v.x, v.y);
                *(__half2*)&Msh[rowi][col] = hv;
            }
        }
    }
    __syncthreads();

    // scatter: warp w -> rows [8w, 8w+8); one float4 atomic per row per lane
#pragma unroll
    for (int rr = 0; rr < 8; ++rr) {
        int row = warp * 8 + rr;
        int r = r_sh[row];
        if (r < 0) continue;
        uint2 hw = *(const uint2*)&Msh[row][ln * 4];
        float2 f0 = __half22float2(*(__half2*)&hw.x);
        float2 f1 = __half22float2(*(__half2*)&hw.y);
        float4 v = make_float4(f0.x, f0.y, f1.x, f1.y);
        atomicAdd((float4*)(g_agg + (size_t)r * 128 + ln * 4), v);
    }
}

__global__ void zero_agg(int n4) {
    int i = blockIdx.x * 256 + threadIdx.x;
    if (i < n4) ((float4*)g_agg)[i] = make_float4(0.f, 0.f, 0.f, 0.f);
}

// ============================================================================
// Host launch: kernel launches ONLY (graph-capture safe).
// ============================================================================
extern "C" void kernel_launch(void* const* d_in, const int* in_sizes, int n_in,
                              void* d_out, int out_size)
{
    const float* h_ptr  = (const float*)d_in[0];
    const float* coords = (const float*)d_in[1];
    const int*   ei     = (const int*)d_in[2];   // int32 (JAX downcasts int64)
    const float* W1     = (const float*)d_in[3];
    const float* b1     = (const float*)d_in[4];
    const float* W2     = (const float*)d_in[5];
    const float* b2     = (const float*)d_in[6];
    const float* U1     = (const float*)d_in[7];
    const float* c1     = (const float*)d_in[8];
    const float* U2     = (const float*)d_in[9];
    const float* c2     = (const float*)d_in[10];

    int N = in_sizes[0] / 128;
    int E = in_sizes[2] / 2;
    int mt = (N + 127) / 128;

    prep_w2<<<32, 256>>>(W2);

    // P = h @ W1[:, :128]^T ; Q = h @ W1[:, 128:256]^T  -> fp16 buffers
    gemm_node<<<mt, 256>>>(h_ptr, 0, W1, 257, 0, nullptr, 0,
                           nullptr, nullptr, nullptr, 1, N, 3);
    gemm_node<<<mt, 256>>>(h_ptr, 0, W1 + 128, 257, 0, nullptr, 0,
                           nullptr, nullptr, nullptr, 2, N, 3);

    int n4 = N * 32;  // N*128/4
    zero_agg<<<(n4 + 255) / 256, 256>>>(n4);

    edge_kernel<<<(E + 63) / 64, 256>>>(coords, ei, W1, b1, b2, E);

    // u1 = silu(h @ U1a^T + agg @ U1b^T + c1)
    gemm_node<<<mt, 256>>>(h_ptr, 0, U1, 256, 3, U1 + 128, 256,
                           c1, nullptr, nullptr, 4, N, 1);
    // out = h + u1 @ U2^T + c2
    gemm_node<<<mt, 256>>>(nullptr, 4, U2, 128, 0, nullptr, 0,
                           c2, h_ptr, (float*)d_out, 0, N, 2);
}